// round 2
// baseline (speedup 1.0000x reference)
#include <cuda_runtime.h>
#include <math.h>

// Problem constants (fixed by the dataset)
constexpr int E     = 256;
constexpr int BATCH = 512;
constexpr int NNEG  = 2048;

// Scratch (allocation-free rule: __device__ globals)
__device__ float g_a[BATCH * E];   // hhat * r_h
__device__ float g_b[BATCH * E];   // r_t
__device__ float g_t[NNEG * E];    // that (normalized tails)

// ---------------------------------------------------------------------------
// Prep 1: normalize head rows, gather relation halves, form a = hhat*r_h, b = r_t
// one block per i, 256 threads (one per e)
// NOTE: relation_id is int32 on the wire (JAX x64-disabled downcasts int64).
// ---------------------------------------------------------------------------
__global__ void prep_head_kernel(const float* __restrict__ head,
                                 const float* __restrict__ rel,
                                 const int* __restrict__ rid) {
    int i = blockIdx.x;
    int e = threadIdx.x;
    float h = head[i * E + e];

    float ss = h * h;
    #pragma unroll
    for (int o = 16; o > 0; o >>= 1)
        ss += __shfl_xor_sync(0xffffffffu, ss, o);

    __shared__ float ws[8];
    int w = e >> 5, l = e & 31;
    if (l == 0) ws[w] = ss;
    __syncthreads();
    float tot = ws[0] + ws[1] + ws[2] + ws[3] + ws[4] + ws[5] + ws[6] + ws[7];

    float n  = sqrtf(tot);
    float hn = h / fmaxf(n, 1e-12f);

    int r = rid[i];
    float rh = rel[r * (2 * E) + e];
    float rt = rel[r * (2 * E) + E + e];

    g_a[i * E + e] = hn * rh;
    g_b[i * E + e] = rt;
}

// ---------------------------------------------------------------------------
// Prep 2: normalize tail rows. one block per j, 256 threads.
// ---------------------------------------------------------------------------
__global__ void prep_tail_kernel(const float* __restrict__ tail) {
    int j = blockIdx.x;
    int e = threadIdx.x;
    float t = tail[j * E + e];

    float ss = t * t;
    #pragma unroll
    for (int o = 16; o > 0; o >>= 1)
        ss += __shfl_xor_sync(0xffffffffu, ss, o);

    __shared__ float ws[8];
    int w = e >> 5, l = e & 31;
    if (l == 0) ws[w] = ss;
    __syncthreads();
    float tot = ws[0] + ws[1] + ws[2] + ws[3] + ws[4] + ws[5] + ws[6] + ws[7];

    float n = sqrtf(tot);
    g_t[j * E + e] = t / fmaxf(n, 1e-12f);
}

// ---------------------------------------------------------------------------
// Main: out[i,j] = -sqrt( sum_k (t[j,k]*b[i,k] - a[i,k])^2 )
// Block tile: BI=64 (i) x BJ=128 (j), 256 threads, thread tile 4x8,
// K staged in chunks of 32 through padded smem.
// ---------------------------------------------------------------------------
constexpr int BI  = 64;
constexpr int BJ  = 128;
constexpr int KC  = 32;
constexpr int LDK = KC + 1;   // padded row stride (floats)

__global__ __launch_bounds__(256, 1) void pairre_main_kernel(float* __restrict__ out) {
    __shared__ float sa[BI * LDK];
    __shared__ float sb[BI * LDK];
    __shared__ float st[BJ * LDK];

    const int tid = threadIdx.x;
    const int tx  = tid & 15;    // j-lane: covers j = tx + 16*c, c in 0..7
    const int ty  = tid >> 4;    // i-lane: covers i = ty + 16*r, r in 0..3
    const int ib  = blockIdx.y * BI;
    const int jb  = blockIdx.x * BJ;

    float acc[4][8];
    #pragma unroll
    for (int r = 0; r < 4; r++)
        #pragma unroll
        for (int c = 0; c < 8; c++)
            acc[r][c] = 0.0f;

    // staging mapping: kcol4 = (tid&7)*4 -> coalesced LDG.128 along k
    const int kc4 = (tid & 7) * 4;
    const int row0 = tid >> 3;   // 0..31

    for (int k0 = 0; k0 < E; k0 += KC) {
        // a,b tiles: 64 rows x 32 k, 2 float4 per thread
        #pragma unroll
        for (int rr = 0; rr < 2; rr++) {
            int ii = row0 + rr * 32;
            float4 va = *reinterpret_cast<const float4*>(&g_a[(ib + ii) * E + k0 + kc4]);
            float4 vb = *reinterpret_cast<const float4*>(&g_b[(ib + ii) * E + k0 + kc4]);
            sa[ii * LDK + kc4 + 0] = va.x;
            sa[ii * LDK + kc4 + 1] = va.y;
            sa[ii * LDK + kc4 + 2] = va.z;
            sa[ii * LDK + kc4 + 3] = va.w;
            sb[ii * LDK + kc4 + 0] = vb.x;
            sb[ii * LDK + kc4 + 1] = vb.y;
            sb[ii * LDK + kc4 + 2] = vb.z;
            sb[ii * LDK + kc4 + 3] = vb.w;
        }
        // t tile: 128 rows x 32 k, 4 float4 per thread
        #pragma unroll
        for (int rr = 0; rr < 4; rr++) {
            int jj = row0 + rr * 32;
            float4 vt = *reinterpret_cast<const float4*>(&g_t[(jb + jj) * E + k0 + kc4]);
            st[jj * LDK + kc4 + 0] = vt.x;
            st[jj * LDK + kc4 + 1] = vt.y;
            st[jj * LDK + kc4 + 2] = vt.z;
            st[jj * LDK + kc4 + 3] = vt.w;
        }
        __syncthreads();

        #pragma unroll 8
        for (int kk = 0; kk < KC; kk++) {
            float ra[4], rb[4], rt[8];
            #pragma unroll
            for (int r = 0; r < 4; r++) {
                int ii = ty + r * 16;
                ra[r] = sa[ii * LDK + kk];
                rb[r] = sb[ii * LDK + kk];
            }
            #pragma unroll
            for (int c = 0; c < 8; c++) {
                int jj = tx + c * 16;
                rt[c] = st[jj * LDK + kk];
            }
            #pragma unroll
            for (int r = 0; r < 4; r++)
                #pragma unroll
                for (int c = 0; c < 8; c++) {
                    float d = fmaf(rt[c], rb[r], -ra[r]);
                    acc[r][c] = fmaf(d, d, acc[r][c]);
                }
        }
        __syncthreads();
    }

    #pragma unroll
    for (int r = 0; r < 4; r++) {
        int i = ib + ty + r * 16;
        #pragma unroll
        for (int c = 0; c < 8; c++) {
            int j = jb + tx + c * 16;
            out[i * NNEG + j] = -sqrtf(acc[r][c]);
        }
    }
}

// ---------------------------------------------------------------------------
// Launch
// ---------------------------------------------------------------------------
extern "C" void kernel_launch(void* const* d_in, const int* in_sizes, int n_in,
                              void* d_out, int out_size) {
    const float* head = (const float*)d_in[0];   // (512, 256)
    const float* tail = (const float*)d_in[1];   // (1, 2048, 256)
    const float* rel  = (const float*)d_in[2];   // (1000, 512)
    const int*   rid  = (const int*)d_in[3];     // (512,) int32 on the wire
    float* out = (float*)d_out;                  // (512, 2048)

    prep_head_kernel<<<BATCH, 256>>>(head, rel, rid);
    prep_tail_kernel<<<NNEG, 256>>>(tail);

    dim3 grid(NNEG / BJ, BATCH / BI);   // (16, 8) = 128 blocks
    pairre_main_kernel<<<grid, 256>>>(out);
}

// round 4
// speedup vs baseline: 1.1923x; 1.1923x over previous
#include <cuda_runtime.h>
#include <math.h>

// Problem constants (fixed by the dataset)
constexpr int E     = 256;
constexpr int BATCH = 512;
constexpr int NNEG  = 2048;

// Scratch (allocation-free rule: __device__ globals)
__device__ float g_na[BATCH * E];  // -(hhat * r_h)   (negated so inner loop is fma(t,b,na))
__device__ float g_b [BATCH * E];  // r_t
__device__ float g_t [NNEG  * E];  // that (normalized tails)

// packed fp32x2 FMA (Blackwell FFMA2 — only reachable via PTX)
#define FMA_F32X2(out, x, y, z) \
    asm("fma.rn.f32x2 %0, %1, %2, %3;" : "=l"(out) : "l"(x), "l"(y), "l"(z))

// ---------------------------------------------------------------------------
// Fused prep: warp-per-row, no block reduction, no smem.
// Rows 0..511      -> head rows  (normalize, gather rel, write -a and b)
// Rows 512..2559   -> tail rows  (normalize, write t)
// 2560 warps = 320 blocks x 8 warps.
// ---------------------------------------------------------------------------
__global__ __launch_bounds__(256) void prep_kernel(const float* __restrict__ head,
                                                   const float* __restrict__ tail,
                                                   const float* __restrict__ rel,
                                                   const int*   __restrict__ rid) {
    const int warp = blockIdx.x * 8 + (threadIdx.x >> 5);
    const int lane = threadIdx.x & 31;
    const int e0 = lane * 4;          // first float4
    const int e1 = lane * 4 + 128;    // second float4

    if (warp < BATCH) {
        const int i = warp;
        float4 h0 = *reinterpret_cast<const float4*>(&head[i * E + e0]);
        float4 h1 = *reinterpret_cast<const float4*>(&head[i * E + e1]);
        float ss = h0.x*h0.x + h0.y*h0.y + h0.z*h0.z + h0.w*h0.w
                 + h1.x*h1.x + h1.y*h1.y + h1.z*h1.z + h1.w*h1.w;
        #pragma unroll
        for (int o = 16; o > 0; o >>= 1)
            ss += __shfl_xor_sync(0xffffffffu, ss, o);
        float inv = 1.0f / fmaxf(sqrtf(ss), 1e-12f);

        int r = rid[i];
        const float* rrow = &rel[(long)r * (2 * E)];
        float4 rh0 = *reinterpret_cast<const float4*>(&rrow[e0]);
        float4 rh1 = *reinterpret_cast<const float4*>(&rrow[e1]);
        float4 rt0 = *reinterpret_cast<const float4*>(&rrow[E + e0]);
        float4 rt1 = *reinterpret_cast<const float4*>(&rrow[E + e1]);

        float4 na0, na1;
        na0.x = -(h0.x * inv) * rh0.x;  na0.y = -(h0.y * inv) * rh0.y;
        na0.z = -(h0.z * inv) * rh0.z;  na0.w = -(h0.w * inv) * rh0.w;
        na1.x = -(h1.x * inv) * rh1.x;  na1.y = -(h1.y * inv) * rh1.y;
        na1.z = -(h1.z * inv) * rh1.z;  na1.w = -(h1.w * inv) * rh1.w;

        *reinterpret_cast<float4*>(&g_na[i * E + e0]) = na0;
        *reinterpret_cast<float4*>(&g_na[i * E + e1]) = na1;
        *reinterpret_cast<float4*>(&g_b [i * E + e0]) = rt0;
        *reinterpret_cast<float4*>(&g_b [i * E + e1]) = rt1;
    } else if (warp < BATCH + NNEG) {
        const int j = warp - BATCH;
        float4 t0 = *reinterpret_cast<const float4*>(&tail[j * E + e0]);
        float4 t1 = *reinterpret_cast<const float4*>(&tail[j * E + e1]);
        float ss = t0.x*t0.x + t0.y*t0.y + t0.z*t0.z + t0.w*t0.w
                 + t1.x*t1.x + t1.y*t1.y + t1.z*t1.z + t1.w*t1.w;
        #pragma unroll
        for (int o = 16; o > 0; o >>= 1)
            ss += __shfl_xor_sync(0xffffffffu, ss, o);
        float inv = 1.0f / fmaxf(sqrtf(ss), 1e-12f);

        t0.x *= inv; t0.y *= inv; t0.z *= inv; t0.w *= inv;
        t1.x *= inv; t1.y *= inv; t1.z *= inv; t1.w *= inv;
        *reinterpret_cast<float4*>(&g_t[j * E + e0]) = t0;
        *reinterpret_cast<float4*>(&g_t[j * E + e1]) = t1;
    }
}

// ---------------------------------------------------------------------------
// Main: out[i,j] = -sqrt( sum_k (t[j,k]*b[i,k] - a[i,k])^2 )
// Block tile BI=64 x BJ=128, 256 threads, 4x8 thread tile.
// K packed in fp32x2 pairs -> FFMA2 pipe (2 FMA/lane/instr).
// ---------------------------------------------------------------------------
constexpr int BI  = 64;
constexpr int BJ  = 128;
constexpr int KC  = 32;
constexpr int LDK = KC + 2;   // 34: even pad -> 8B-aligned k-pairs, conflict-free 64b LDS

typedef unsigned long long u64;

__global__ __launch_bounds__(256, 1) void pairre_main_kernel(float* __restrict__ out) {
    __shared__ __align__(16) float sna[BI * LDK];
    __shared__ __align__(16) float sb [BI * LDK];
    __shared__ __align__(16) float st [BJ * LDK];

    const int tid = threadIdx.x;
    const int tx  = tid & 15;    // j-lane: j = tx + 16*c
    const int ty  = tid >> 4;    // i-lane: i = ty + 16*r
    const int ib  = blockIdx.y * BI;
    const int jb  = blockIdx.x * BJ;

    u64 acc[4][8];
    #pragma unroll
    for (int r = 0; r < 4; r++)
        #pragma unroll
        for (int c = 0; c < 8; c++)
            acc[r][c] = 0ull;

    // staging mapping: coalesced float4 LDG along k, stored as 2x float2
    const int kc4  = (tid & 7) * 4;
    const int row0 = tid >> 3;   // 0..31

    for (int k0 = 0; k0 < E; k0 += KC) {
        #pragma unroll
        for (int rr = 0; rr < 2; rr++) {
            int ii = row0 + rr * 32;
            float4 va = *reinterpret_cast<const float4*>(&g_na[(ib + ii) * E + k0 + kc4]);
            float4 vb = *reinterpret_cast<const float4*>(&g_b [(ib + ii) * E + k0 + kc4]);
            *reinterpret_cast<float2*>(&sna[ii * LDK + kc4    ]) = make_float2(va.x, va.y);
            *reinterpret_cast<float2*>(&sna[ii * LDK + kc4 + 2]) = make_float2(va.z, va.w);
            *reinterpret_cast<float2*>(&sb [ii * LDK + kc4    ]) = make_float2(vb.x, vb.y);
            *reinterpret_cast<float2*>(&sb [ii * LDK + kc4 + 2]) = make_float2(vb.z, vb.w);
        }
        #pragma unroll
        for (int rr = 0; rr < 4; rr++) {
            int jj = row0 + rr * 32;
            float4 vt = *reinterpret_cast<const float4*>(&g_t[(jb + jj) * E + k0 + kc4]);
            *reinterpret_cast<float2*>(&st[jj * LDK + kc4    ]) = make_float2(vt.x, vt.y);
            *reinterpret_cast<float2*>(&st[jj * LDK + kc4 + 2]) = make_float2(vt.z, vt.w);
        }
        __syncthreads();

        #pragma unroll
        for (int kk2 = 0; kk2 < KC / 2; kk2++) {
            u64 rna[4], rb[4], rt[8];
            #pragma unroll
            for (int r = 0; r < 4; r++) {
                int ii = ty + r * 16;
                rna[r] = *reinterpret_cast<const u64*>(&sna[ii * LDK + 2 * kk2]);
                rb [r] = *reinterpret_cast<const u64*>(&sb [ii * LDK + 2 * kk2]);
            }
            #pragma unroll
            for (int c = 0; c < 8; c++) {
                int jj = tx + c * 16;
                rt[c] = *reinterpret_cast<const u64*>(&st[jj * LDK + 2 * kk2]);
            }
            #pragma unroll
            for (int r = 0; r < 4; r++)
                #pragma unroll
                for (int c = 0; c < 8; c++) {
                    u64 d;
                    FMA_F32X2(d, rt[c], rb[r], rna[r]);   // d = t*b + (-a), both halves
                    FMA_F32X2(acc[r][c], d, d, acc[r][c]);
                }
        }
        __syncthreads();
    }

    #pragma unroll
    for (int r = 0; r < 4; r++) {
        int i = ib + ty + r * 16;
        #pragma unroll
        for (int c = 0; c < 8; c++) {
            int j = jb + tx + c * 16;
            float2 v = *reinterpret_cast<float2*>(&acc[r][c]);
            out[i * NNEG + j] = -sqrtf(v.x + v.y);
        }
    }
}

// ---------------------------------------------------------------------------
// Launch
// ---------------------------------------------------------------------------
extern "C" void kernel_launch(void* const* d_in, const int* in_sizes, int n_in,
                              void* d_out, int out_size) {
    const float* head = (const float*)d_in[0];   // (512, 256)
    const float* tail = (const float*)d_in[1];   // (1, 2048, 256)
    const float* rel  = (const float*)d_in[2];   // (1000, 512)
    const int*   rid  = (const int*)d_in[3];     // (512,) int32 on the wire
    float* out = (float*)d_out;                  // (512, 2048)

    prep_kernel<<<(BATCH + NNEG) / 8, 256>>>(head, tail, rel, rid);

    dim3 grid(NNEG / BJ, BATCH / BI);   // (16, 8) = 128 blocks
    pairre_main_kernel<<<grid, 256>>>(out);
}

// round 6
// speedup vs baseline: 2.0981x; 1.7597x over previous
#include <cuda_runtime.h>
#include <math.h>
#include <stdint.h>

// ---------------------------------------------------------------------------
// Problem constants
// ---------------------------------------------------------------------------
constexpr int E     = 256;
constexpr int BATCH = 512;
constexpr int NNEG  = 2048;
constexpr int K2    = 512;           // expanded GEMM K

// Scratch (__device__ globals: allocation-free rule)
__device__ float g_A[BATCH * K2];    // [b^2 | -2ab]  (tf32-rounded)
__device__ float g_T[NNEG  * K2];    // [t^2 | t]     (tf32-rounded)
__device__ float g_alpha[BATCH];     // sum a^2

__device__ __forceinline__ float to_tf32(float x) {
    uint32_t u;
    asm("cvt.rna.tf32.f32 %0, %1;" : "=r"(u) : "f"(x));
    return __uint_as_float(u);
}
__device__ __forceinline__ uint32_t smem_u32(const void* p) {
    uint32_t a;
    asm("{ .reg .u64 t; cvta.to.shared.u64 t, %1; cvt.u32.u64 %0, t; }" : "=r"(a) : "l"(p));
    return a;
}

#define CP_ASYNC16(sm, gp) \
    asm volatile("cp.async.cg.shared.global [%0], [%1], 16;" :: "r"(sm), "l"(gp) : "memory")
#define CP_COMMIT() asm volatile("cp.async.commit_group;" ::: "memory")
#define CP_WAIT(n)  asm volatile("cp.async.wait_group %0;" :: "n"(n) : "memory")

// ---------------------------------------------------------------------------
// Prep: warp-per-row. head rows -> A' = [b^2 | -2ab], alpha; tail rows -> T' = [t^2 | t]
// ---------------------------------------------------------------------------
__global__ __launch_bounds__(256) void prep_kernel(const float* __restrict__ head,
                                                   const float* __restrict__ tail,
                                                   const float* __restrict__ rel,
                                                   const int*   __restrict__ rid) {
    const int warp = blockIdx.x * 8 + (threadIdx.x >> 5);
    const int lane = threadIdx.x & 31;
    const int e0 = lane * 4;
    const int e1 = lane * 4 + 128;

    if (warp < BATCH) {
        const int i = warp;
        float4 h0 = *reinterpret_cast<const float4*>(&head[i * E + e0]);
        float4 h1 = *reinterpret_cast<const float4*>(&head[i * E + e1]);
        float ss = h0.x*h0.x + h0.y*h0.y + h0.z*h0.z + h0.w*h0.w
                 + h1.x*h1.x + h1.y*h1.y + h1.z*h1.z + h1.w*h1.w;
        #pragma unroll
        for (int o = 16; o > 0; o >>= 1) ss += __shfl_xor_sync(0xffffffffu, ss, o);
        float inv = 1.0f / fmaxf(sqrtf(ss), 1e-12f);

        int r = rid[i];
        const float* rrow = &rel[(long)r * (2 * E)];
        float4 rh0 = *reinterpret_cast<const float4*>(&rrow[e0]);
        float4 rh1 = *reinterpret_cast<const float4*>(&rrow[e1]);
        float4 rt0 = *reinterpret_cast<const float4*>(&rrow[E + e0]);
        float4 rt1 = *reinterpret_cast<const float4*>(&rrow[E + e1]);

        float a[8], b[8];
        a[0]=(h0.x*inv)*rh0.x; a[1]=(h0.y*inv)*rh0.y; a[2]=(h0.z*inv)*rh0.z; a[3]=(h0.w*inv)*rh0.w;
        a[4]=(h1.x*inv)*rh1.x; a[5]=(h1.y*inv)*rh1.y; a[6]=(h1.z*inv)*rh1.z; a[7]=(h1.w*inv)*rh1.w;
        b[0]=rt0.x; b[1]=rt0.y; b[2]=rt0.z; b[3]=rt0.w;
        b[4]=rt1.x; b[5]=rt1.y; b[6]=rt1.z; b[7]=rt1.w;

        float asq = 0.0f;
        #pragma unroll
        for (int q = 0; q < 8; q++) asq += a[q] * a[q];
        #pragma unroll
        for (int o = 16; o > 0; o >>= 1) asq += __shfl_xor_sync(0xffffffffu, asq, o);
        if (lane == 0) g_alpha[i] = asq;

        float4 bb0 = make_float4(to_tf32(b[0]*b[0]), to_tf32(b[1]*b[1]), to_tf32(b[2]*b[2]), to_tf32(b[3]*b[3]));
        float4 bb1 = make_float4(to_tf32(b[4]*b[4]), to_tf32(b[5]*b[5]), to_tf32(b[6]*b[6]), to_tf32(b[7]*b[7]));
        float4 ab0 = make_float4(to_tf32(-2.f*a[0]*b[0]), to_tf32(-2.f*a[1]*b[1]), to_tf32(-2.f*a[2]*b[2]), to_tf32(-2.f*a[3]*b[3]));
        float4 ab1 = make_float4(to_tf32(-2.f*a[4]*b[4]), to_tf32(-2.f*a[5]*b[5]), to_tf32(-2.f*a[6]*b[6]), to_tf32(-2.f*a[7]*b[7]));

        *reinterpret_cast<float4*>(&g_A[i * K2 + e0])       = bb0;
        *reinterpret_cast<float4*>(&g_A[i * K2 + e1])       = bb1;
        *reinterpret_cast<float4*>(&g_A[i * K2 + 256 + e0]) = ab0;
        *reinterpret_cast<float4*>(&g_A[i * K2 + 256 + e1]) = ab1;
    } else if (warp < BATCH + NNEG) {
        const int j = warp - BATCH;
        float4 t0 = *reinterpret_cast<const float4*>(&tail[j * E + e0]);
        float4 t1 = *reinterpret_cast<const float4*>(&tail[j * E + e1]);
        float ss = t0.x*t0.x + t0.y*t0.y + t0.z*t0.z + t0.w*t0.w
                 + t1.x*t1.x + t1.y*t1.y + t1.z*t1.z + t1.w*t1.w;
        #pragma unroll
        for (int o = 16; o > 0; o >>= 1) ss += __shfl_xor_sync(0xffffffffu, ss, o);
        float inv = 1.0f / fmaxf(sqrtf(ss), 1e-12f);

        t0.x *= inv; t0.y *= inv; t0.z *= inv; t0.w *= inv;
        t1.x *= inv; t1.y *= inv; t1.z *= inv; t1.w *= inv;

        float4 q0 = make_float4(to_tf32(t0.x*t0.x), to_tf32(t0.y*t0.y), to_tf32(t0.z*t0.z), to_tf32(t0.w*t0.w));
        float4 q1 = make_float4(to_tf32(t1.x*t1.x), to_tf32(t1.y*t1.y), to_tf32(t1.z*t1.z), to_tf32(t1.w*t1.w));
        float4 l0 = make_float4(to_tf32(t0.x), to_tf32(t0.y), to_tf32(t0.z), to_tf32(t0.w));
        float4 l1 = make_float4(to_tf32(t1.x), to_tf32(t1.y), to_tf32(t1.z), to_tf32(t1.w));

        *reinterpret_cast<float4*>(&g_T[j * K2 + e0])       = q0;
        *reinterpret_cast<float4*>(&g_T[j * K2 + e1])       = q1;
        *reinterpret_cast<float4*>(&g_T[j * K2 + 256 + e0]) = l0;
        *reinterpret_cast<float4*>(&g_T[j * K2 + 256 + e1]) = l1;
    }
}

// ---------------------------------------------------------------------------
// Main: tf32 mma.sync GEMM. CTA tile 64x128, 8 warps (2x4), warp tile 32x32.
// K=512 in 16 chunks of 32, double-buffered via cp.async.
// Epilogue: out = -sqrt(max(D + alpha, 0)).
// ---------------------------------------------------------------------------
constexpr int BM  = 64;
constexpr int BN  = 128;
constexpr int BK  = 32;
constexpr int LDK = 36;                       // padded row (floats); 144B: 16B-aligned, conflict-free frags
constexpr int A_WORDS = BM * LDK;             // 2304
constexpr int B_WORDS = BN * LDK;             // 4608
constexpr int BUF_WORDS = A_WORDS + B_WORDS;  // 6912
constexpr int SMEM_BYTES = 2 * BUF_WORDS * 4; // 55296

__device__ __forceinline__ void mma_tf32(float d[4], const uint32_t a[4], const uint32_t b[2]) {
    asm volatile(
        "mma.sync.aligned.m16n8k8.row.col.f32.tf32.tf32.f32 "
        "{%0,%1,%2,%3}, {%4,%5,%6,%7}, {%8,%9}, {%0,%1,%2,%3};"
        : "+f"(d[0]), "+f"(d[1]), "+f"(d[2]), "+f"(d[3])
        : "r"(a[0]), "r"(a[1]), "r"(a[2]), "r"(a[3]), "r"(b[0]), "r"(b[1]));
}

__global__ __launch_bounds__(256, 1) void pairre_mma_kernel(float* __restrict__ out) {
    extern __shared__ __align__(16) float smem[];
    const uint32_t sb = smem_u32(smem);

    const int tid  = threadIdx.x;
    const int wid  = tid >> 5;
    const int lane = tid & 31;
    const int ib = blockIdx.y * BM;
    const int jb = blockIdx.x * BN;

    const int wm = (wid >> 2) * 32;     // warp m offset (0/32)
    const int wn = (wid & 3) * 32;      // warp n offset (0..96)
    const int g  = lane >> 2;           // group id 0..7
    const int t  = lane & 3;            // thread-in-group 0..3

    // staging: each thread fills 2 A-rows + 4 B-rows, one float4 each
    const int srow = tid >> 3;          // 0..31
    const int sc4  = (tid & 7) * 4;     // k-word 0..28

    float d[2][4][4];
    #pragma unroll
    for (int ma = 0; ma < 2; ma++)
        #pragma unroll
        for (int na = 0; na < 4; na++)
            #pragma unroll
            for (int q = 0; q < 4; q++)
                d[ma][na][q] = 0.0f;

    auto issue_chunk = [&](int c, int bsel) {
        const int k0 = c * BK;
        const uint32_t bufA = sb + (bsel * BUF_WORDS) * 4;
        const uint32_t bufB = sb + (bsel * BUF_WORDS + A_WORDS) * 4;
        #pragma unroll
        for (int rr = 0; rr < 2; rr++) {
            int r = srow + rr * 32;
            CP_ASYNC16(bufA + (r * LDK + sc4) * 4, &g_A[(ib + r) * K2 + k0 + sc4]);
        }
        #pragma unroll
        for (int rr = 0; rr < 4; rr++) {
            int r = srow + rr * 32;
            CP_ASYNC16(bufB + (r * LDK + sc4) * 4, &g_T[(jb + r) * K2 + k0 + sc4]);
        }
        CP_COMMIT();
    };

    issue_chunk(0, 0);

    for (int c = 0; c < K2 / BK; c++) {
        const int bsel = c & 1;
        if (c + 1 < K2 / BK) {
            issue_chunk(c + 1, bsel ^ 1);
            CP_WAIT(1);
        } else {
            CP_WAIT(0);
        }
        __syncthreads();

        const float* fA = smem + bsel * BUF_WORDS;
        const float* fB = smem + bsel * BUF_WORDS + A_WORDS;

        #pragma unroll
        for (int ks = 0; ks < BK / 8; ks++) {
            const int kk = ks * 8;
            uint32_t afr[2][4], bfr[4][2];
            #pragma unroll
            for (int ma = 0; ma < 2; ma++) {
                int m = wm + ma * 16 + g;
                afr[ma][0] = __float_as_uint(fA[m * LDK + kk + t]);
                afr[ma][1] = __float_as_uint(fA[(m + 8) * LDK + kk + t]);
                afr[ma][2] = __float_as_uint(fA[m * LDK + kk + t + 4]);
                afr[ma][3] = __float_as_uint(fA[(m + 8) * LDK + kk + t + 4]);
            }
            #pragma unroll
            for (int na = 0; na < 4; na++) {
                int n = wn + na * 8 + g;
                bfr[na][0] = __float_as_uint(fB[n * LDK + kk + t]);
                bfr[na][1] = __float_as_uint(fB[n * LDK + kk + t + 4]);
            }
            #pragma unroll
            for (int ma = 0; ma < 2; ma++)
                #pragma unroll
                for (int na = 0; na < 4; na++)
                    mma_tf32(d[ma][na], afr[ma], bfr[na]);
        }
        __syncthreads();
    }

    // Epilogue: out[i,j] = -sqrt(max(d + alpha_i, 0))
    #pragma unroll
    for (int ma = 0; ma < 2; ma++) {
        const int i0 = ib + wm + ma * 16 + g;
        const float al0 = g_alpha[i0];
        const float al1 = g_alpha[i0 + 8];
        #pragma unroll
        for (int na = 0; na < 4; na++) {
            const int j = jb + wn + na * 8 + t * 2;
            float2 v0, v1;
            v0.x = -sqrtf(fmaxf(d[ma][na][0] + al0, 0.0f));
            v0.y = -sqrtf(fmaxf(d[ma][na][1] + al0, 0.0f));
            v1.x = -sqrtf(fmaxf(d[ma][na][2] + al1, 0.0f));
            v1.y = -sqrtf(fmaxf(d[ma][na][3] + al1, 0.0f));
            *reinterpret_cast<float2*>(&out[i0 * NNEG + j])       = v0;
            *reinterpret_cast<float2*>(&out[(i0 + 8) * NNEG + j]) = v1;
        }
    }
}

// ---------------------------------------------------------------------------
// Launch
// ---------------------------------------------------------------------------
extern "C" void kernel_launch(void* const* d_in, const int* in_sizes, int n_in,
                              void* d_out, int out_size) {
    const float* head = (const float*)d_in[0];   // (512, 256)
    const float* tail = (const float*)d_in[1];   // (1, 2048, 256)
    const float* rel  = (const float*)d_in[2];   // (1000, 512)
    const int*   rid  = (const int*)d_in[3];     // (512,) int32 on the wire
    float* out = (float*)d_out;                  // (512, 2048)

    cudaFuncSetAttribute(pairre_mma_kernel,
                         cudaFuncAttributeMaxDynamicSharedMemorySize, SMEM_BYTES);

    prep_kernel<<<(BATCH + NNEG) / 8, 256>>>(head, tail, rel, rid);

    dim3 grid(NNEG / BN, BATCH / BM);   // (16, 8) = 128 CTAs
    pairre_mma_kernel<<<grid, 256, SMEM_BYTES>>>(out);
}